// round 5
// baseline (speedup 1.0000x reference)
#include <cuda_runtime.h>
#include <math.h>

#define NB     8192
#define NPTS   16384
#define TILE   256
#define NTILES 64
#define NPAIRS (NTILES * (NTILES + 1) / 2)   // 2080
#define KBLK   256
#define KGRID  64                             // blocks 0..31 base, 32..63 target
#define NCELLS 1024                           // 32x32 Morton grid
#define HSLOTS (NCELLS * KGRID)               // 65536, cell-major
#define CUT    40.0f                          // skip if min d_q^2 > CUT (k < 2^-40)

struct MmdConsts {
    float sq;                  // sqrt(inv * log2e)
    float sx, sy;              // exp(log_scale)
    float mxb, myb, mxt, myt;  // weighted means (scaled space)
    float invUb, invUt;
    float gate;
    float ox, oy, icwx, icwy;  // q-space grid origin + inverse cell width
};

__device__ float     g_u[NPTS];
__device__ float     g_bp[KGRID * 8];   // U,Sx,Sy,minx,maxx,miny,maxy,pad
__device__ float4    g_pts[NPTS];       // unsorted (qx,qy,B,s)
__device__ float4    g_sorted[NPTS];    // sorted by Morton cell
__device__ unsigned  g_cell[NPTS];
__device__ unsigned  g_hist[HSLOTS];
__device__ float     g_partial[NPAIRS];
__device__ MmdConsts g_c;

__device__ __forceinline__ float ex2f(float x) {
    float y;
    asm("ex2.approx.ftz.f32 %0, %1;" : "=f"(y) : "f"(x));
    return y;
}
__device__ __forceinline__ float softplusf(float x) {
    return fmaxf(x, 0.0f) + log1pf(expf(-fabsf(x)));
}
__device__ __forceinline__ unsigned part1by1(unsigned x) {
    x &= 0x0000ffffu;
    x = (x | (x << 8)) & 0x00FF00FFu;
    x = (x | (x << 4)) & 0x0F0F0F0Fu;
    x = (x | (x << 2)) & 0x33333333u;
    x = (x | (x << 1)) & 0x55555555u;
    return x;
}

// ---------------------------------------------------------------------------
// K1: node-weight MLP + per-block partials (U, Sx, Sy, bbox) + zero g_hist.
// ---------------------------------------------------------------------------
__global__ void k1_weights(const float* __restrict__ bfeat,
                           const float* __restrict__ tfeat,
                           const float* __restrict__ bpos,
                           const float* __restrict__ tpos,
                           const float* __restrict__ w1,
                           const float* __restrict__ b1,
                           const float* __restrict__ w2,
                           const float* __restrict__ b2)
{
    int t = threadIdx.x;
    int i = blockIdx.x * KBLK + t;
    ((uint4*)g_hist)[i] = make_uint4(0u, 0u, 0u, 0u);   // zero hist (4 per thread)

    bool isb = (i < NB);
    const float* feat = isb ? (bfeat + i * 5) : (tfeat + (i - NB) * 5);
    const float* pos  = isb ? (bpos + i * 2)  : (tpos + (i - NB) * 2);
    float px = pos[0], py = pos[1];

    float f0 = feat[0], f1 = feat[1], f2 = feat[2], f3 = feat[3], f4 = feat[4];
    float logit = __ldg(b2);
#pragma unroll
    for (int j = 0; j < 32; j++) {
        float h = __ldg(b1 + j);
        h = fmaf(f0, __ldg(w1 + 0 * 32 + j), h);
        h = fmaf(f1, __ldg(w1 + 1 * 32 + j), h);
        h = fmaf(f2, __ldg(w1 + 2 * 32 + j), h);
        h = fmaf(f3, __ldg(w1 + 3 * 32 + j), h);
        h = fmaf(f4, __ldg(w1 + 4 * 32 + j), h);
        h = fmaxf(h, 0.0f);
        logit = fmaf(h, __ldg(w2 + j), logit);
    }
    float u = softplusf(logit) + 1e-6f;
    g_u[i] = u;

    __shared__ float sh[7][KBLK];
    sh[0][t] = u;
    sh[1][t] = u * px;
    sh[2][t] = u * py;
    sh[3][t] = px;  sh[4][t] = px;
    sh[5][t] = py;  sh[6][t] = py;
    __syncthreads();
    for (int s = KBLK / 2; s > 0; s >>= 1) {
        if (t < s) {
            sh[0][t] += sh[0][t + s];
            sh[1][t] += sh[1][t + s];
            sh[2][t] += sh[2][t + s];
            sh[3][t] = fminf(sh[3][t], sh[3][t + s]);
            sh[4][t] = fmaxf(sh[4][t], sh[4][t + s]);
            sh[5][t] = fminf(sh[5][t], sh[5][t + s]);
            sh[6][t] = fmaxf(sh[6][t], sh[6][t + s]);
        }
        __syncthreads();
    }
    if (t < 7) g_bp[blockIdx.x * 8 + t] = sh[t][0];
}

// ---------------------------------------------------------------------------
// K2: reduce partials -> consts (means, bbox in q-space, grid) + gate.
// ---------------------------------------------------------------------------
__global__ void k2_consts(const float* __restrict__ bdesc,
                          const float* __restrict__ tdesc,
                          const float* __restrict__ g1,
                          const float* __restrict__ gb1,
                          const float* __restrict__ g2,
                          const float* __restrict__ gb2,
                          const float* __restrict__ log_sigma,
                          const float* __restrict__ log_scale)
{
    int t = threadIdx.x;  // block of 64
    __shared__ float sh[7][64];
#pragma unroll
    for (int q = 0; q < 7; q++) sh[q][t] = g_bp[t * 8 + q];
    __syncthreads();
    // reduce base half [0,32) and target half [32,64) independently
    for (int s = 16; s > 0; s >>= 1) {
        if ((t & 31) < s) {
            sh[0][t] += sh[0][t + s];
            sh[1][t] += sh[1][t + s];
            sh[2][t] += sh[2][t + s];
            sh[3][t] = fminf(sh[3][t], sh[3][t + s]);
            sh[4][t] = fmaxf(sh[4][t], sh[4][t + s]);
            sh[5][t] = fminf(sh[5][t], sh[5][t + s]);
            sh[6][t] = fmaxf(sh[6][t], sh[6][t + s]);
        }
        __syncthreads();
    }

    // gate: warp 0, one hidden unit per lane
    float gsum = 0.0f;
    if (t < 32) {
        float d0 = fabsf(bdesc[0] - tdesc[0]);
        float d1 = fabsf(bdesc[1] - tdesc[1]);
        float d2 = fabsf(bdesc[2] - tdesc[2]);
        float d3 = fabsf(bdesc[3] - tdesc[3]);
        float h = gb1[t];
        h = fmaf(d0, g1[0 * 32 + t], h);
        h = fmaf(d1, g1[1 * 32 + t], h);
        h = fmaf(d2, g1[2 * 32 + t], h);
        h = fmaf(d3, g1[3 * 32 + t], h);
        h = fmaxf(h, 0.0f);
        gsum = h * g2[t];
        for (int o = 16; o > 0; o >>= 1) gsum += __shfl_xor_sync(0xffffffffu, gsum, o);
    }

    if (t == 0) {
        float Ub = sh[0][0],  Sxb = sh[1][0],  Syb = sh[2][0];
        float bnx = sh[3][0], bxx = sh[4][0], bny = sh[5][0], bxy = sh[6][0];
        float Ut = sh[0][32], Sxt = sh[1][32], Syt = sh[2][32];
        float tnx = sh[3][32], txx = sh[4][32], tny = sh[5][32], txy = sh[6][32];

        float sx = expf(log_scale[0]);
        float sy = expf(log_scale[1]);
        float sigma = expf(log_sigma[0]);
        float inv = 1.0f / (2.0f * sigma * sigma);
        float cc = inv * 1.44269504088896340736f;
        float sq = sqrtf(cc);

        MmdConsts c;
        c.sq = sq; c.sx = sx; c.sy = sy;
        c.mxb = sx * Sxb / Ub;  c.myb = sy * Syb / Ub;
        c.mxt = sx * Sxt / Ut;  c.myt = sy * Syt / Ut;
        c.invUb = 1.0f / Ub;    c.invUt = 1.0f / Ut;

        // q-space bbox union (monotonic transform per cloud)
        float qbnx = (bnx * sx - c.mxb) * sq, qbxx = (bxx * sx - c.mxb) * sq;
        float qtnx = (tnx * sx - c.mxt) * sq, qtxx = (txx * sx - c.mxt) * sq;
        float qbny = (bny * sy - c.myb) * sq, qbxy = (bxy * sy - c.myb) * sq;
        float qtny = (tny * sy - c.myt) * sq, qtxy = (txy * sy - c.myt) * sq;
        float minx = fminf(qbnx, qtnx), maxx = fmaxf(qbxx, qtxx);
        float miny = fminf(qbny, qtny), maxy = fmaxf(qbxy, qtxy);
        c.ox = minx; c.oy = miny;
        c.icwx = 31.9999f / fmaxf(maxx - minx, 1e-30f);
        c.icwy = 31.9999f / fmaxf(maxy - miny, 1e-30f);

        c.gate = softplusf(gsum + gb2[0]) + 1e-6f;
        g_c = c;
    }
}

// ---------------------------------------------------------------------------
// K3: per-point (qx,qy,B,s), Morton cell id, per-block cell histogram.
// ---------------------------------------------------------------------------
__global__ void k3_prep(const float* __restrict__ bpos,
                        const float* __restrict__ tpos)
{
    int i = blockIdx.x * KBLK + threadIdx.x;
    MmdConsts c = g_c;
    bool isb = (i < NB);
    const float* pos = isb ? (bpos + i * 2) : (tpos + (i - NB) * 2);
    float qx = (pos[0] * c.sx - (isb ? c.mxb : c.mxt)) * c.sq;
    float qy = (pos[1] * c.sy - (isb ? c.myb : c.myt)) * c.sq;
    float B  = -(fmaf(qx, qx, qy * qy));
    float s  = g_u[i] * (isb ? c.invUb : -c.invUt);
    g_pts[i] = make_float4(qx, qy, B, s);

    int ix = (int)((qx - c.ox) * c.icwx);
    int iy = (int)((qy - c.oy) * c.icwy);
    ix = max(0, min(31, ix));
    iy = max(0, min(31, iy));
    unsigned cell = (part1by1((unsigned)iy) << 1) | part1by1((unsigned)ix);
    g_cell[i] = cell;
    atomicAdd(&g_hist[cell * KGRID + blockIdx.x], 1u);
}

// ---------------------------------------------------------------------------
// K4s: exclusive scan of g_hist (65536 entries), single block of 1024.
// ---------------------------------------------------------------------------
__global__ void k4_scan()
{
    int t = threadIdx.x;
    int base = t * 64;
    unsigned tot = 0;
    for (int e = 0; e < 64; e++) tot += g_hist[base + e];

    __shared__ unsigned s[1024];
    s[t] = tot;
    __syncthreads();
    for (int off = 1; off < 1024; off <<= 1) {
        unsigned v = (t >= off) ? s[t - off] : 0u;
        __syncthreads();
        s[t] += v;
        __syncthreads();
    }
    unsigned run = s[t] - tot;   // exclusive prefix of this thread's chunk
    for (int e = 0; e < 64; e++) {
        unsigned v = g_hist[base + e];
        g_hist[base + e] = run;
        run += v;
    }
}

// ---------------------------------------------------------------------------
// K5s: stable deterministic scatter into g_sorted.
// ---------------------------------------------------------------------------
__global__ void k5_scatter()
{
    int b = blockIdx.x, t = threadIdx.x;
    int i = b * KBLK + t;
    unsigned cell = g_cell[i];
    __shared__ unsigned sc[KBLK];
    sc[t] = cell;
    __syncthreads();
    int cnt = 0;
    for (int j = 0; j < t; j++) cnt += (sc[j] == cell) ? 1 : 0;
    unsigned pos = g_hist[cell * KGRID + b] + (unsigned)cnt;
    g_sorted[pos] = g_pts[i];
}

// ---------------------------------------------------------------------------
// K6: symmetric tiled MMD with 32x32 warp-group AABB culling.
// ---------------------------------------------------------------------------
__global__ void __launch_bounds__(TILE) k6_mmd()
{
    int rem = blockIdx.x;
    int bi = 0;
    while (rem >= NTILES - bi) { rem -= NTILES - bi; bi++; }
    int bj = bi + rem;

    int t = threadIdx.x, lane = t & 31, wid = t >> 5;

    __shared__ float4 sj[TILE];
    __shared__ float4 sjA[8];     // j-group AABBs: (minx,miny,maxx,maxy)
    __shared__ float  red[TILE];

    float4 pj = g_sorted[bj * TILE + t];
    sj[t] = pj;
    // warp wid owns j-group wid (its own 32 loaded points)
    float jnx = pj.x, jxx = pj.x, jny = pj.y, jxy = pj.y;
    for (int o = 16; o > 0; o >>= 1) {
        jnx = fminf(jnx, __shfl_xor_sync(0xffffffffu, jnx, o));
        jxx = fmaxf(jxx, __shfl_xor_sync(0xffffffffu, jxx, o));
        jny = fminf(jny, __shfl_xor_sync(0xffffffffu, jny, o));
        jxy = fmaxf(jxy, __shfl_xor_sync(0xffffffffu, jxy, o));
    }
    if (lane == 0) sjA[wid] = make_float4(jnx, jny, jxx, jxy);

    float4 pi = g_sorted[bi * TILE + t];
    float inx = pi.x, ixx = pi.x, iny = pi.y, ixy = pi.y;
    for (int o = 16; o > 0; o >>= 1) {
        inx = fminf(inx, __shfl_xor_sync(0xffffffffu, inx, o));
        ixx = fmaxf(ixx, __shfl_xor_sync(0xffffffffu, ixx, o));
        iny = fminf(iny, __shfl_xor_sync(0xffffffffu, iny, o));
        ixy = fmaxf(ixy, __shfl_xor_sync(0xffffffffu, ixy, o));
    }
    __syncthreads();

    float xi2 = 2.0f * pi.x;
    float yi2 = 2.0f * pi.y;
    float Bi  = pi.z;
    float si  = pi.w;

    float acc = 0.0f;
#pragma unroll
    for (int g = 0; g < 8; g++) {
        float4 A = sjA[g];  // minx,miny,maxx,maxy
        float dx = fmaxf(0.0f, fmaxf(A.x - ixx, inx - A.z));
        float dy = fmaxf(0.0f, fmaxf(A.y - ixy, iny - A.w));
        if (fmaf(dx, dx, dy * dy) < CUT) {   // warp-uniform
#pragma unroll
            for (int jj = 0; jj < 32; jj++) {
                float4 p = sj[g * 32 + jj];
                float a = Bi + p.z;
                a = fmaf(yi2, p.y, a);
                a = fmaf(xi2, p.x, a);
                float k = ex2f(a);
                acc = fmaf(p.w, k, acc);
            }
        }
    }
    float val = si * acc;

    red[t] = val;
    __syncthreads();
    for (int s = TILE / 2; s > 0; s >>= 1) {
        if (t < s) red[t] += red[t + s];
        __syncthreads();
    }
    if (t == 0)
        g_partial[blockIdx.x] = (bi == bj) ? red[0] : 2.0f * red[0];
}

// ---------------------------------------------------------------------------
// K7: final deterministic reduce (double), apply gate + bias.
// ---------------------------------------------------------------------------
__global__ void k7_final(const float* __restrict__ bias, float* __restrict__ out)
{
    __shared__ double red[256];
    double a = 0.0;
    for (int i = threadIdx.x; i < NPAIRS; i += 256) a += (double)g_partial[i];
    red[threadIdx.x] = a;
    __syncthreads();
    for (int s = 128; s > 0; s >>= 1) {
        if (threadIdx.x < s) red[threadIdx.x] += red[threadIdx.x + s];
        __syncthreads();
    }
    if (threadIdx.x == 0)
        out[0] = (float)(red[0] * (double)g_c.gate + (double)bias[0]);
}

// ---------------------------------------------------------------------------
extern "C" void kernel_launch(void* const* d_in, const int* in_sizes, int n_in,
                              void* d_out, int out_size)
{
    const float* base_pos    = (const float*)d_in[0];
    const float* base_feat   = (const float*)d_in[1];
    const float* base_desc   = (const float*)d_in[2];
    const float* target_pos  = (const float*)d_in[3];
    const float* target_feat = (const float*)d_in[4];
    const float* target_desc = (const float*)d_in[5];
    const float* w1  = (const float*)d_in[6];
    const float* b1  = (const float*)d_in[7];
    const float* w2  = (const float*)d_in[8];
    const float* b2  = (const float*)d_in[9];
    const float* g1  = (const float*)d_in[10];
    const float* gb1 = (const float*)d_in[11];
    const float* g2  = (const float*)d_in[12];
    const float* gb2 = (const float*)d_in[13];
    const float* log_sigma = (const float*)d_in[14];
    const float* log_scale = (const float*)d_in[15];
    const float* bias      = (const float*)d_in[16];
    float* out = (float*)d_out;

    k1_weights<<<KGRID, KBLK>>>(base_feat, target_feat, base_pos, target_pos,
                                w1, b1, w2, b2);
    k2_consts<<<1, 64>>>(base_desc, target_desc, g1, gb1, g2, gb2,
                         log_sigma, log_scale);
    k3_prep<<<KGRID, KBLK>>>(base_pos, target_pos);
    k4_scan<<<1, 1024>>>();
    k5_scatter<<<KGRID, KBLK>>>();
    k6_mmd<<<NPAIRS, TILE>>>();
    k7_final<<<1, 256>>>(bias, out);
}

// round 7
// speedup vs baseline: 3.1403x; 3.1403x over previous
#include <cuda_runtime.h>
#include <math.h>

#define NB     8192
#define NPTS   16384
#define TILE   256
#define NTILES 64
#define NPAIRS (NTILES * (NTILES + 1) / 2)   // 2080
#define KBLK   256
#define KGRID  64                             // blocks 0..31 base, 32..63 target
#define NCELLS 1024                           // 32x32 Morton grid
#define HSLOTS (NCELLS * KGRID)               // 65536, cell-major
#define CUT    40.0f                          // skip if min d_q^2 > CUT (k < 2^-40)

struct MmdConsts {
    float sq;                  // sqrt(inv * log2e)
    float sx, sy;              // exp(log_scale)
    float mxb, myb, mxt, myt;  // weighted means (scaled space)
    float invUb, invUt;
    float gate;
    float ox, oy, icwx, icwy;  // q-space grid origin + inverse cell width
};

__device__ float     g_u[NPTS];
__device__ float     g_bp[KGRID * 8];   // U,Sx,Sy,minx,maxx,miny,maxy,pad
__device__ float4    g_pts[NPTS];       // unsorted (qx,qy,B,s)
__device__ float4    g_sorted[NPTS];    // sorted by Morton cell
__device__ unsigned  g_cell[NPTS];
__device__ unsigned  g_hist[HSLOTS];
__device__ unsigned  g_bsum[256];
__device__ unsigned  g_boff[256];
__device__ float     g_partial[NPAIRS];
__device__ MmdConsts g_c;

__device__ __forceinline__ float ex2f(float x) {
    float y;
    asm("ex2.approx.ftz.f32 %0, %1;" : "=f"(y) : "f"(x));
    return y;
}
__device__ __forceinline__ float softplusf(float x) {
    return fmaxf(x, 0.0f) + log1pf(expf(-fabsf(x)));
}
__device__ __forceinline__ unsigned part1by1(unsigned x) {
    x &= 0x0000ffffu;
    x = (x | (x << 8)) & 0x00FF00FFu;
    x = (x | (x << 4)) & 0x0F0F0F0Fu;
    x = (x | (x << 2)) & 0x33333333u;
    x = (x | (x << 1)) & 0x55555555u;
    return x;
}

// ---------------------------------------------------------------------------
// K1: node-weight MLP + per-block partials (U, Sx, Sy, bbox) + zero g_hist.
// ---------------------------------------------------------------------------
__global__ void k1_weights(const float* __restrict__ bfeat,
                           const float* __restrict__ tfeat,
                           const float* __restrict__ bpos,
                           const float* __restrict__ tpos,
                           const float* __restrict__ w1,
                           const float* __restrict__ b1,
                           const float* __restrict__ w2,
                           const float* __restrict__ b2)
{
    int t = threadIdx.x;
    int i = blockIdx.x * KBLK + t;
    ((uint4*)g_hist)[i] = make_uint4(0u, 0u, 0u, 0u);   // zero hist (4 per thread)

    bool isb = (i < NB);
    const float* feat = isb ? (bfeat + i * 5) : (tfeat + (i - NB) * 5);
    const float* pos  = isb ? (bpos + i * 2)  : (tpos + (i - NB) * 2);
    float px = pos[0], py = pos[1];

    float f0 = feat[0], f1 = feat[1], f2 = feat[2], f3 = feat[3], f4 = feat[4];
    float logit = __ldg(b2);
#pragma unroll
    for (int j = 0; j < 32; j++) {
        float h = __ldg(b1 + j);
        h = fmaf(f0, __ldg(w1 + 0 * 32 + j), h);
        h = fmaf(f1, __ldg(w1 + 1 * 32 + j), h);
        h = fmaf(f2, __ldg(w1 + 2 * 32 + j), h);
        h = fmaf(f3, __ldg(w1 + 3 * 32 + j), h);
        h = fmaf(f4, __ldg(w1 + 4 * 32 + j), h);
        h = fmaxf(h, 0.0f);
        logit = fmaf(h, __ldg(w2 + j), logit);
    }
    float u = softplusf(logit) + 1e-6f;
    g_u[i] = u;

    __shared__ float sh[7][KBLK];
    sh[0][t] = u;
    sh[1][t] = u * px;
    sh[2][t] = u * py;
    sh[3][t] = px;  sh[4][t] = px;
    sh[5][t] = py;  sh[6][t] = py;
    __syncthreads();
    for (int s = KBLK / 2; s > 0; s >>= 1) {
        if (t < s) {
            sh[0][t] += sh[0][t + s];
            sh[1][t] += sh[1][t + s];
            sh[2][t] += sh[2][t + s];
            sh[3][t] = fminf(sh[3][t], sh[3][t + s]);
            sh[4][t] = fmaxf(sh[4][t], sh[4][t + s]);
            sh[5][t] = fminf(sh[5][t], sh[5][t + s]);
            sh[6][t] = fmaxf(sh[6][t], sh[6][t + s]);
        }
        __syncthreads();
    }
    if (t < 7) g_bp[blockIdx.x * 8 + t] = sh[t][0];
}

// ---------------------------------------------------------------------------
// K2: reduce partials -> consts (means, bbox in q-space, grid) + gate.
// ---------------------------------------------------------------------------
__global__ void k2_consts(const float* __restrict__ bdesc,
                          const float* __restrict__ tdesc,
                          const float* __restrict__ g1,
                          const float* __restrict__ gb1,
                          const float* __restrict__ g2,
                          const float* __restrict__ gb2,
                          const float* __restrict__ log_sigma,
                          const float* __restrict__ log_scale)
{
    int t = threadIdx.x;  // block of 64
    __shared__ float sh[7][64];
#pragma unroll
    for (int q = 0; q < 7; q++) sh[q][t] = g_bp[t * 8 + q];
    __syncthreads();
    // reduce base half [0,32) and target half [32,64) independently
    for (int s = 16; s > 0; s >>= 1) {
        if ((t & 31) < s) {
            sh[0][t] += sh[0][t + s];
            sh[1][t] += sh[1][t + s];
            sh[2][t] += sh[2][t + s];
            sh[3][t] = fminf(sh[3][t], sh[3][t + s]);
            sh[4][t] = fmaxf(sh[4][t], sh[4][t + s]);
            sh[5][t] = fminf(sh[5][t], sh[5][t + s]);
            sh[6][t] = fmaxf(sh[6][t], sh[6][t + s]);
        }
        __syncthreads();
    }

    // gate: warp 0, one hidden unit per lane
    float gsum = 0.0f;
    if (t < 32) {
        float d0 = fabsf(bdesc[0] - tdesc[0]);
        float d1 = fabsf(bdesc[1] - tdesc[1]);
        float d2 = fabsf(bdesc[2] - tdesc[2]);
        float d3 = fabsf(bdesc[3] - tdesc[3]);
        float h = gb1[t];
        h = fmaf(d0, g1[0 * 32 + t], h);
        h = fmaf(d1, g1[1 * 32 + t], h);
        h = fmaf(d2, g1[2 * 32 + t], h);
        h = fmaf(d3, g1[3 * 32 + t], h);
        h = fmaxf(h, 0.0f);
        gsum = h * g2[t];
        for (int o = 16; o > 0; o >>= 1) gsum += __shfl_xor_sync(0xffffffffu, gsum, o);
    }

    if (t == 0) {
        float Ub = sh[0][0],  Sxb = sh[1][0],  Syb = sh[2][0];
        float bnx = sh[3][0], bxx = sh[4][0], bny = sh[5][0], bxy = sh[6][0];
        float Ut = sh[0][32], Sxt = sh[1][32], Syt = sh[2][32];
        float tnx = sh[3][32], txx = sh[4][32], tny = sh[5][32], txy = sh[6][32];

        float sx = expf(log_scale[0]);
        float sy = expf(log_scale[1]);
        float sigma = expf(log_sigma[0]);
        float inv = 1.0f / (2.0f * sigma * sigma);
        float cc = inv * 1.44269504088896340736f;
        float sq = sqrtf(cc);

        MmdConsts c;
        c.sq = sq; c.sx = sx; c.sy = sy;
        c.mxb = sx * Sxb / Ub;  c.myb = sy * Syb / Ub;
        c.mxt = sx * Sxt / Ut;  c.myt = sy * Syt / Ut;
        c.invUb = 1.0f / Ub;    c.invUt = 1.0f / Ut;

        // q-space bbox union (monotonic transform per cloud)
        float qbnx = (bnx * sx - c.mxb) * sq, qbxx = (bxx * sx - c.mxb) * sq;
        float qtnx = (tnx * sx - c.mxt) * sq, qtxx = (txx * sx - c.mxt) * sq;
        float qbny = (bny * sy - c.myb) * sq, qbxy = (bxy * sy - c.myb) * sq;
        float qtny = (tny * sy - c.myt) * sq, qtxy = (txy * sy - c.myt) * sq;
        float minx = fminf(qbnx, qtnx), maxx = fmaxf(qbxx, qtxx);
        float miny = fminf(qbny, qtny), maxy = fmaxf(qbxy, qtxy);
        c.ox = minx; c.oy = miny;
        c.icwx = 31.9999f / fmaxf(maxx - minx, 1e-30f);
        c.icwy = 31.9999f / fmaxf(maxy - miny, 1e-30f);

        c.gate = softplusf(gsum + gb2[0]) + 1e-6f;
        g_c = c;
    }
}

// ---------------------------------------------------------------------------
// K3: per-point (qx,qy,B,s), Morton cell id, per-block cell histogram.
// ---------------------------------------------------------------------------
__global__ void k3_prep(const float* __restrict__ bpos,
                        const float* __restrict__ tpos)
{
    int i = blockIdx.x * KBLK + threadIdx.x;
    MmdConsts c = g_c;
    bool isb = (i < NB);
    const float* pos = isb ? (bpos + i * 2) : (tpos + (i - NB) * 2);
    float qx = (pos[0] * c.sx - (isb ? c.mxb : c.mxt)) * c.sq;
    float qy = (pos[1] * c.sy - (isb ? c.myb : c.myt)) * c.sq;
    float B  = -(fmaf(qx, qx, qy * qy));
    float s  = g_u[i] * (isb ? c.invUb : -c.invUt);
    g_pts[i] = make_float4(qx, qy, B, s);

    int ix = (int)((qx - c.ox) * c.icwx);
    int iy = (int)((qy - c.oy) * c.icwy);
    ix = max(0, min(31, ix));
    iy = max(0, min(31, iy));
    unsigned cell = (part1by1((unsigned)iy) << 1) | part1by1((unsigned)ix);
    g_cell[i] = cell;
    atomicAdd(&g_hist[cell * KGRID + blockIdx.x], 1u);
}

// ---------------------------------------------------------------------------
// K4a: phase-1 scan. 256 blocks x 256 threads, 1 element each.
//      In-place exclusive-within-block + per-block totals.
// ---------------------------------------------------------------------------
__global__ void k4a_scan()
{
    int t = threadIdx.x;
    int gid = blockIdx.x * 256 + t;
    unsigned v = g_hist[gid];
    __shared__ unsigned s[256];
    s[t] = v;
    __syncthreads();
#pragma unroll
    for (int off = 1; off < 256; off <<= 1) {
        unsigned add = (t >= off) ? s[t - off] : 0u;
        __syncthreads();
        s[t] += add;
        __syncthreads();
    }
    g_hist[gid] = s[t] - v;               // exclusive within block
    if (t == 255) g_bsum[blockIdx.x] = s[255];
}

// ---------------------------------------------------------------------------
// K4b: phase-2 scan of the 256 block totals (single block).
// ---------------------------------------------------------------------------
__global__ void k4b_scan()
{
    int t = threadIdx.x;
    unsigned v = g_bsum[t];
    __shared__ unsigned s[256];
    s[t] = v;
    __syncthreads();
#pragma unroll
    for (int off = 1; off < 256; off <<= 1) {
        unsigned add = (t >= off) ? s[t - off] : 0u;
        __syncthreads();
        s[t] += add;
        __syncthreads();
    }
    g_boff[t] = s[t] - v;                 // exclusive block offset
}

// ---------------------------------------------------------------------------
// K5: stable deterministic scatter (phase-3 offset add fused here).
// ---------------------------------------------------------------------------
__global__ void k5_scatter()
{
    int b = blockIdx.x, t = threadIdx.x;
    int i = b * KBLK + t;
    unsigned cell = g_cell[i];
    __shared__ unsigned sc[KBLK];
    sc[t] = cell;
    __syncthreads();
    int cnt = 0;
    for (int j = 0; j < t; j++) cnt += (sc[j] == cell) ? 1 : 0;
    unsigned slot = cell * KGRID + b;
    unsigned pos = g_hist[slot] + g_boff[slot >> 8] + (unsigned)cnt;
    g_sorted[pos] = g_pts[i];
}

// ---------------------------------------------------------------------------
// K6: symmetric tiled MMD with 32x32 warp-group AABB culling.
// ---------------------------------------------------------------------------
__global__ void __launch_bounds__(TILE) k6_mmd()
{
    int rem = blockIdx.x;
    int bi = 0;
    while (rem >= NTILES - bi) { rem -= NTILES - bi; bi++; }
    int bj = bi + rem;

    int t = threadIdx.x, lane = t & 31, wid = t >> 5;

    __shared__ float4 sj[TILE];
    __shared__ float4 sjA[8];     // j-group AABBs: (minx,miny,maxx,maxy)
    __shared__ float  red[TILE];

    float4 pj = g_sorted[bj * TILE + t];
    sj[t] = pj;
    // warp wid owns j-group wid (its own 32 loaded points)
    float jnx = pj.x, jxx = pj.x, jny = pj.y, jxy = pj.y;
    for (int o = 16; o > 0; o >>= 1) {
        jnx = fminf(jnx, __shfl_xor_sync(0xffffffffu, jnx, o));
        jxx = fmaxf(jxx, __shfl_xor_sync(0xffffffffu, jxx, o));
        jny = fminf(jny, __shfl_xor_sync(0xffffffffu, jny, o));
        jxy = fmaxf(jxy, __shfl_xor_sync(0xffffffffu, jxy, o));
    }
    if (lane == 0) sjA[wid] = make_float4(jnx, jny, jxx, jxy);

    float4 pi = g_sorted[bi * TILE + t];
    float inx = pi.x, ixx = pi.x, iny = pi.y, ixy = pi.y;
    for (int o = 16; o > 0; o >>= 1) {
        inx = fminf(inx, __shfl_xor_sync(0xffffffffu, inx, o));
        ixx = fmaxf(ixx, __shfl_xor_sync(0xffffffffu, ixx, o));
        iny = fminf(iny, __shfl_xor_sync(0xffffffffu, iny, o));
        ixy = fmaxf(ixy, __shfl_xor_sync(0xffffffffu, ixy, o));
    }
    __syncthreads();

    float xi2 = 2.0f * pi.x;
    float yi2 = 2.0f * pi.y;
    float Bi  = pi.z;
    float si  = pi.w;

    float acc = 0.0f;
#pragma unroll
    for (int g = 0; g < 8; g++) {
        float4 A = sjA[g];  // minx,miny,maxx,maxy
        float dx = fmaxf(0.0f, fmaxf(A.x - ixx, inx - A.z));
        float dy = fmaxf(0.0f, fmaxf(A.y - ixy, iny - A.w));
        if (fmaf(dx, dx, dy * dy) < CUT) {   // warp-uniform
#pragma unroll
            for (int jj = 0; jj < 32; jj++) {
                float4 p = sj[g * 32 + jj];
                float a = Bi + p.z;
                a = fmaf(yi2, p.y, a);
                a = fmaf(xi2, p.x, a);
                float k = ex2f(a);
                acc = fmaf(p.w, k, acc);
            }
        }
    }
    float val = si * acc;

    red[t] = val;
    __syncthreads();
    for (int s = TILE / 2; s > 0; s >>= 1) {
        if (t < s) red[t] += red[t + s];
        __syncthreads();
    }
    if (t == 0)
        g_partial[blockIdx.x] = (bi == bj) ? red[0] : 2.0f * red[0];
}

// ---------------------------------------------------------------------------
// K7: final deterministic reduce (double), apply gate + bias.
// ---------------------------------------------------------------------------
__global__ void k7_final(const float* __restrict__ bias, float* __restrict__ out)
{
    __shared__ double red[256];
    double a = 0.0;
    for (int i = threadIdx.x; i < NPAIRS; i += 256) a += (double)g_partial[i];
    red[threadIdx.x] = a;
    __syncthreads();
    for (int s = 128; s > 0; s >>= 1) {
        if (threadIdx.x < s) red[threadIdx.x] += red[threadIdx.x + s];
        __syncthreads();
    }
    if (threadIdx.x == 0)
        out[0] = (float)(red[0] * (double)g_c.gate + (double)bias[0]);
}

// ---------------------------------------------------------------------------
extern "C" void kernel_launch(void* const* d_in, const int* in_sizes, int n_in,
                              void* d_out, int out_size)
{
    const float* base_pos    = (const float*)d_in[0];
    const float* base_feat   = (const float*)d_in[1];
    const float* base_desc   = (const float*)d_in[2];
    const float* target_pos  = (const float*)d_in[3];
    const float* target_feat = (const float*)d_in[4];
    const float* target_desc = (const float*)d_in[5];
    const float* w1  = (const float*)d_in[6];
    const float* b1  = (const float*)d_in[7];
    const float* w2  = (const float*)d_in[8];
    const float* b2  = (const float*)d_in[9];
    const float* g1  = (const float*)d_in[10];
    const float* gb1 = (const float*)d_in[11];
    const float* g2  = (const float*)d_in[12];
    const float* gb2 = (const float*)d_in[13];
    const float* log_sigma = (const float*)d_in[14];
    const float* log_scale = (const float*)d_in[15];
    const float* bias      = (const float*)d_in[16];
    float* out = (float*)d_out;

    k1_weights<<<KGRID, KBLK>>>(base_feat, target_feat, base_pos, target_pos,
                                w1, b1, w2, b2);
    k2_consts<<<1, 64>>>(base_desc, target_desc, g1, gb1, g2, gb2,
                         log_sigma, log_scale);
    k3_prep<<<KGRID, KBLK>>>(base_pos, target_pos);
    k4a_scan<<<256, 256>>>();
    k4b_scan<<<1, 256>>>();
    k5_scatter<<<KGRID, KBLK>>>();
    k6_mmd<<<NPAIRS, TILE>>>();
    k7_final<<<1, 256>>>(bias, out);
}